// round 7
// baseline (speedup 1.0000x reference)
#include <cuda_runtime.h>
#include <cuda_bf16.h>

// Problem: B=500000, F=32, U=48, S=1000, H=24
// Output: concat( out[B,1], new_state[S,48] ) -> float32

#define ULL unsigned long long
#define CAP 4096
#define NCHUNK 4
#define BIN_CTAS 64

__device__ float g_G[1000 * 144];       // state @ gru_rec_kernel
__device__ int   g_winner[1000];        // last (max) row index per slot
__device__ int   g_count[1000];
__device__ int   g_perm[1000 * CAP];    // padded bins

// ---------- packed f32x2 helpers ----------
__device__ __forceinline__ ULL pk2(float lo, float hi) {
    ULL r; asm("mov.b64 %0, {%1, %2};" : "=l"(r) : "f"(lo), "f"(hi)); return r;
}
__device__ __forceinline__ float2 up2(ULL v) {
    float2 r; asm("mov.b64 {%0, %1}, %2;" : "=f"(r.x), "=f"(r.y) : "l"(v)); return r;
}
__device__ __forceinline__ ULL fma2(ULL a, ULL b, ULL c) {
    ULL d; asm("fma.rn.f32x2 %0, %1, %2, %3;" : "=l"(d) : "l"(a), "l"(b), "l"(c)); return d;
}
__device__ __forceinline__ float hsum2(ULL v) { float2 f = up2(v); return f.x + f.y; }

__device__ __forceinline__ float sigmoidf(float x) {
    return __fdividef(1.0f, 1.0f + __expf(-x));
}
__device__ __forceinline__ float tanh_fast(float x) {
    return fmaf(2.0f, __fdividef(1.0f, 1.0f + __expf(-2.0f * x)), -1.0f);
}

// ---------- kernel 0: fused prep (blocks 0..999) + binning (blocks 1000..1063) ----------
__global__ void __launch_bounds__(256)
setup_kernel(const float* __restrict__ state,
             const float* __restrict__ Urec,
             float* __restrict__ out_state,
             const int* __restrict__ ids, int B) {
    const int tid = threadIdx.x;
    if (blockIdx.x < 1000) {
        const int s = blockIdx.x;
        __shared__ float hs[48];
        if (tid < 48) {
            float v = state[s * 48 + tid];
            hs[tid] = v;
            out_state[s * 48 + tid] = v;
        }
        if (tid == 0) { g_winner[s] = -1; g_count[s] = 0; }
        __syncthreads();
        if (tid < 144) {
            float acc = 0.0f;
            #pragma unroll
            for (int u = 0; u < 48; u++)
                acc = fmaf(hs[u], Urec[u * 144 + tid], acc);
            g_G[s * 144 + tid] = acc;
        }
    } else {
        __shared__ int lcnt[1000];
        __shared__ int lmax[1000];
        __shared__ int lbase[1000];
        const int cta = blockIdx.x - 1000;
        const int per = (B + BIN_CTAS - 1) / BIN_CTAS;
        const int lo = cta * per;
        const int hi = min(B, lo + per);

        for (int s = tid; s < 1000; s += 256) { lcnt[s] = 0; lmax[s] = -1; }
        __syncthreads();

        for (int b = lo + tid; b < hi; b += 256) {
            int id = ids[b];
            atomicAdd(&lcnt[id], 1);
            atomicMax(&lmax[id], b);
        }
        __syncthreads();

        for (int s = tid; s < 1000; s += 256) {
            int c = lcnt[s];
            if (c > 0) {
                lbase[s] = atomicAdd(&g_count[s], c);
                atomicMax(&g_winner[s], lmax[s]);
                lcnt[s] = 0;
            }
        }
        __syncthreads();

        for (int b = lo + tid; b < hi; b += 256) {
            int id = ids[b];
            int off = atomicAdd(&lcnt[id], 1);
            int pos = lbase[id] + off;
            if (pos < CAP) g_perm[id * CAP + pos] = b;
        }
    }
}

// ---------- kernel 1: main fused GRU + MLP head ----------
__global__ void __launch_bounds__(96)
main_kernel(const float* __restrict__ inputs,
            const float* __restrict__ state,
            const float* __restrict__ Wk,      // [32,144]
            const float* __restrict__ gbias,   // [144]
            const float* __restrict__ Dw,      // [80,24]
            const float* __restrict__ Db,      // [24]
            const float* __restrict__ Ow,      // [24]
            const float* __restrict__ Ob,      // [1]
            float* __restrict__ out,           // [B]
            float* __restrict__ out_state) {   // [S,48]
    __shared__ __align__(16) float sW[144 * 32];   // sW[j*32+f] = Wk[f,j]
    __shared__ __align__(16) float sD[24 * 80];    // sD[j*80+c] = Dw[c,j]
    __shared__ float sB[144];
    __shared__ float sG[144];
    __shared__ float sh[48];
    __shared__ float sDb[24];
    __shared__ float sOw[24];
    __shared__ float sOb;
    __shared__ __align__(16) ulonglong2 hsh[12 * 96];   // 4 h units / 16B slot per thread

    const int tid   = threadIdx.x;
    const int s     = blockIdx.x >> 2;             // slot
    const int chunk = blockIdx.x & (NCHUNK - 1);

    for (int i = tid; i < 144 * 32; i += 96) {
        int j = i >> 5, f = i & 31;
        sW[i] = Wk[f * 144 + j];
    }
    for (int i = tid; i < 24 * 80; i += 96) {
        int j = i / 80, c = i - j * 80;
        sD[i] = Dw[c * 24 + j];
    }
    for (int i = tid; i < 144; i += 96) { sB[i] = gbias[i]; sG[i] = g_G[s * 144 + i]; }
    if (tid < 48) sh[tid] = state[s * 48 + tid];
    if (tid < 24) { sDb[tid] = Db[tid]; sOw[tid] = Ow[tid]; }
    if (tid == 0) sOb = Ob[0];
    __syncthreads();

    const int cnt    = min(g_count[s], CAP);
    const int winner = g_winner[s];
    const int* bin   = g_perm + s * CAP;

    for (int i = chunk * 96 + tid; i < cnt; i += NCHUNK * 96) {
        const int b = bin[i];

        // load x row as 16 packed pairs (contiguous 128B line)
        ULL x2[16];
        const float4* xr = (const float4*)(inputs + (size_t)b * 32);
        #pragma unroll
        for (int k = 0; k < 8; k++) {
            float4 v = xr[k];
            x2[2 * k]     = pk2(v.x, v.y);
            x2[2 * k + 1] = pk2(v.z, v.w);
        }

        // GRU (rolled): 4 units per iteration -> one STS.128 of packed h_new
        for (int q = 0; q < 12; q++) {
            float hv[4];
            #pragma unroll
            for (int p = 0; p < 4; p++) {
                const int u = 4 * q + p;
                const ulonglong2* wz = (const ulonglong2*)(sW + 32 * u);
                const ulonglong2* wr = (const ulonglong2*)(sW + 32 * (48 + u));
                const ulonglong2* wh = (const ulonglong2*)(sW + 32 * (96 + u));
                ULL az = 0ULL, ar = 0ULL, ah = 0ULL;
                #pragma unroll
                for (int k = 0; k < 8; k++) {
                    ulonglong2 a = wz[k], c = wr[k], e = wh[k];
                    az = fma2(x2[2 * k], a.x, az); az = fma2(x2[2 * k + 1], a.y, az);
                    ar = fma2(x2[2 * k], c.x, ar); ar = fma2(x2[2 * k + 1], c.y, ar);
                    ah = fma2(x2[2 * k], e.x, ah); ah = fma2(x2[2 * k + 1], e.y, ah);
                }
                float gz = hsum2(az) + sB[u]      + sG[u];
                float gr = hsum2(ar) + sB[48 + u] + sG[48 + u];
                float gh = hsum2(ah) + sB[96 + u];
                float z = sigmoidf(gz);
                float r = sigmoidf(gr);
                float hc = tanh_fast(fmaf(r, sG[96 + u], gh));
                float hprev = sh[u];
                hv[p] = z * hprev + (1.0f - z) * hc;
            }
            ulonglong2 hp2;
            hp2.x = pk2(hv[0], hv[1]);
            hp2.y = pk2(hv[2], hv[3]);
            hsh[q * 96 + tid] = hp2;
        }

        // Load h back ONCE into registers (12 LDS.128), then dense head fully
        // unrolled with static register indices for h.
        ULL h2[24];
        #pragma unroll
        for (int m = 0; m < 12; m++) {
            ulonglong2 t = hsh[m * 96 + tid];
            h2[2 * m]     = t.x;
            h2[2 * m + 1] = t.y;
        }

        float o = sOb;
        #pragma unroll
        for (int j = 0; j < 24; j++) {
            const ulonglong2* dj = (const ulonglong2*)(sD + 80 * j);
            ULL acc = 0ULL;
            #pragma unroll
            for (int k = 0; k < 8; k++) {
                ulonglong2 w = dj[k];
                acc = fma2(x2[2 * k], w.x, acc);
                acc = fma2(x2[2 * k + 1], w.y, acc);
            }
            #pragma unroll
            for (int m = 0; m < 12; m++) {
                ulonglong2 w = dj[8 + m];
                acc = fma2(h2[2 * m],     w.x, acc);
                acc = fma2(h2[2 * m + 1], w.y, acc);
            }
            float hid = hsum2(acc) + sDb[j];
            hid = fmaxf(hid, 0.0f);
            o = fmaf(hid, sOw[j], o);
        }
        out[b] = sigmoidf(o);

        // last-wins scatter of h_new from registers
        if (b == winner) {
            float4* os = (float4*)(out_state + s * 48);
            #pragma unroll
            for (int m = 0; m < 12; m++) {
                float2 a = up2(h2[2 * m]), c = up2(h2[2 * m + 1]);
                float4 v; v.x = a.x; v.y = a.y; v.z = c.x; v.w = c.y;
                os[m] = v;
            }
        }
    }
}

extern "C" void kernel_launch(void* const* d_in, const int* in_sizes, int n_in,
                              void* d_out, int out_size) {
    const float* inputs = (const float*)d_in[0];
    const int*   ids    = (const int*)d_in[1];
    const float* state  = (const float*)d_in[2];
    const float* Wk     = (const float*)d_in[3];
    const float* Urec   = (const float*)d_in[4];
    const float* gbias  = (const float*)d_in[5];
    const float* Dw     = (const float*)d_in[6];
    const float* Db     = (const float*)d_in[7];
    const float* Ow     = (const float*)d_in[8];
    const float* Ob     = (const float*)d_in[9];

    const int B = in_sizes[0] / 32;
    const int S = in_sizes[2] / 48;

    float* out       = (float*)d_out;
    float* out_state = out + B;

    setup_kernel<<<S + BIN_CTAS, 256>>>(state, Urec, out_state, ids, B);
    main_kernel<<<S * NCHUNK, 96>>>(inputs, state, Wk, gbias,
                                    Dw, Db, Ow, Ob, out, out_state);
}

// round 8
// speedup vs baseline: 1.4569x; 1.4569x over previous
#include <cuda_runtime.h>
#include <cuda_bf16.h>

// Problem: B=500000, F=32, U=48, S=1000, H=24
// Output: concat( out[B,1], new_state[S,48] ) -> float32

#define ULL unsigned long long
#define CAP 4096
#define NCHUNK 4
#define BIN_CTAS 64

__device__ float g_G[1000 * 144];       // state @ gru_rec_kernel
__device__ int   g_winner[1000];        // last (max) row index per slot
__device__ int   g_count[1000];
__device__ int   g_perm[1000 * CAP];    // padded bins

// ---------- packed f32x2 helpers ----------
__device__ __forceinline__ ULL pk2(float lo, float hi) {
    ULL r; asm("mov.b64 %0, {%1, %2};" : "=l"(r) : "f"(lo), "f"(hi)); return r;
}
__device__ __forceinline__ float2 up2(ULL v) {
    float2 r; asm("mov.b64 {%0, %1}, %2;" : "=f"(r.x), "=f"(r.y) : "l"(v)); return r;
}
__device__ __forceinline__ ULL fma2(ULL a, ULL b, ULL c) {
    ULL d; asm("fma.rn.f32x2 %0, %1, %2, %3;" : "=l"(d) : "l"(a), "l"(b), "l"(c)); return d;
}
__device__ __forceinline__ float hsum2(ULL v) { float2 f = up2(v); return f.x + f.y; }

__device__ __forceinline__ float sigmoidf(float x) {
    return __fdividef(1.0f, 1.0f + __expf(-x));
}
__device__ __forceinline__ float tanh_fast(float x) {
    return fmaf(2.0f, __fdividef(1.0f, 1.0f + __expf(-2.0f * x)), -1.0f);
}

// ---------- kernel 0: fused prep (blocks 0..999) + binning (blocks 1000..1063) ----------
__global__ void __launch_bounds__(256)
setup_kernel(const float* __restrict__ state,
             const float* __restrict__ Urec,
             float* __restrict__ out_state,
             const int* __restrict__ ids, int B) {
    const int tid = threadIdx.x;
    if (blockIdx.x < 1000) {
        const int s = blockIdx.x;
        __shared__ float hs[48];
        if (tid < 48) {
            float v = state[s * 48 + tid];
            hs[tid] = v;
            out_state[s * 48 + tid] = v;
        }
        if (tid == 0) { g_winner[s] = -1; g_count[s] = 0; }
        __syncthreads();
        if (tid < 144) {
            float acc = 0.0f;
            #pragma unroll
            for (int u = 0; u < 48; u++)
                acc = fmaf(hs[u], Urec[u * 144 + tid], acc);
            g_G[s * 144 + tid] = acc;
        }
    } else {
        __shared__ int lcnt[1000];
        __shared__ int lmax[1000];
        __shared__ int lbase[1000];
        const int cta = blockIdx.x - 1000;
        const int per = (B + BIN_CTAS - 1) / BIN_CTAS;
        const int lo = cta * per;
        const int hi = min(B, lo + per);

        for (int s = tid; s < 1000; s += 256) { lcnt[s] = 0; lmax[s] = -1; }
        __syncthreads();

        for (int b = lo + tid; b < hi; b += 256) {
            int id = ids[b];
            atomicAdd(&lcnt[id], 1);
            atomicMax(&lmax[id], b);
        }
        __syncthreads();

        for (int s = tid; s < 1000; s += 256) {
            int c = lcnt[s];
            if (c > 0) {
                lbase[s] = atomicAdd(&g_count[s], c);
                atomicMax(&g_winner[s], lmax[s]);
                lcnt[s] = 0;
            }
        }
        __syncthreads();

        for (int b = lo + tid; b < hi; b += 256) {
            int id = ids[b];
            int off = atomicAdd(&lcnt[id], 1);
            int pos = lbase[id] + off;
            if (pos < CAP) g_perm[id * CAP + pos] = b;
        }
    }
}

// ---------- kernel 1: main fused GRU + MLP head ----------
__global__ void __launch_bounds__(96)
main_kernel(const float* __restrict__ inputs,
            const float* __restrict__ state,
            const float* __restrict__ Wk,      // [32,144]
            const float* __restrict__ gbias,   // [144]
            const float* __restrict__ Dw,      // [80,24]
            const float* __restrict__ Db,      // [24]
            const float* __restrict__ Ow,      // [24]
            const float* __restrict__ Ob,      // [1]
            float* __restrict__ out,           // [B]
            float* __restrict__ out_state) {   // [S,48]
    __shared__ __align__(16) float sW[144 * 32];   // sW[j*32+f] = Wk[f,j]
    __shared__ __align__(16) float sD[24 * 80];    // sD[j*80+c] = Dw[c,j]
    __shared__ float sB[144];
    __shared__ float sG[144];
    __shared__ float sh[48];
    __shared__ float sDb[24];
    __shared__ float sOw[24];
    __shared__ float sOb;
    __shared__ __align__(16) ulonglong2 hsh[12 * 96];   // 4 h units / 16B slot per thread

    const int tid   = threadIdx.x;
    const int s     = blockIdx.x >> 2;             // slot
    const int chunk = blockIdx.x & (NCHUNK - 1);

    for (int i = tid; i < 144 * 32; i += 96) {
        int j = i >> 5, f = i & 31;
        sW[i] = Wk[f * 144 + j];
    }
    for (int i = tid; i < 24 * 80; i += 96) {
        int j = i / 80, c = i - j * 80;
        sD[i] = Dw[c * 24 + j];
    }
    for (int i = tid; i < 144; i += 96) { sB[i] = gbias[i]; sG[i] = g_G[s * 144 + i]; }
    if (tid < 48) sh[tid] = state[s * 48 + tid];
    if (tid < 24) { sDb[tid] = Db[tid]; sOw[tid] = Ow[tid]; }
    if (tid == 0) sOb = Ob[0];
    __syncthreads();

    const int cnt    = min(g_count[s], CAP);
    const int winner = g_winner[s];
    const int* bin   = g_perm + s * CAP;

    for (int i = chunk * 96 + tid; i < cnt; i += NCHUNK * 96) {
        const int b = bin[i];

        // load x row as 16 packed pairs (contiguous 128B line)
        ULL x2[16];
        const float4* xr = (const float4*)(inputs + (size_t)b * 32);
        #pragma unroll
        for (int k = 0; k < 8; k++) {
            float4 v = xr[k];
            x2[2 * k]     = pk2(v.x, v.y);
            x2[2 * k + 1] = pk2(v.z, v.w);
        }

        // GRU (rolled): 4 units per iteration -> one STS.128 of packed h_new
        for (int q = 0; q < 12; q++) {
            float hv[4];
            #pragma unroll
            for (int p = 0; p < 4; p++) {
                const int u = 4 * q + p;
                const ulonglong2* wz = (const ulonglong2*)(sW + 32 * u);
                const ulonglong2* wr = (const ulonglong2*)(sW + 32 * (48 + u));
                const ulonglong2* wh = (const ulonglong2*)(sW + 32 * (96 + u));
                ULL az = 0ULL, ar = 0ULL, ah = 0ULL;
                #pragma unroll
                for (int k = 0; k < 8; k++) {
                    ulonglong2 a = wz[k], c = wr[k], e = wh[k];
                    az = fma2(x2[2 * k], a.x, az); az = fma2(x2[2 * k + 1], a.y, az);
                    ar = fma2(x2[2 * k], c.x, ar); ar = fma2(x2[2 * k + 1], c.y, ar);
                    ah = fma2(x2[2 * k], e.x, ah); ah = fma2(x2[2 * k + 1], e.y, ah);
                }
                float gz = hsum2(az) + sB[u]      + sG[u];
                float gr = hsum2(ar) + sB[48 + u] + sG[48 + u];
                float gh = hsum2(ah) + sB[96 + u];
                float z = sigmoidf(gz);
                float r = sigmoidf(gr);
                float hc = tanh_fast(fmaf(r, sG[96 + u], gh));
                float hprev = sh[u];
                hv[p] = z * hprev + (1.0f - z) * hc;
            }
            ulonglong2 hp2;
            hp2.x = pk2(hv[0], hv[1]);
            hp2.y = pk2(hv[2], hv[3]);
            hsh[q * 96 + tid] = hp2;
        }

        // dense head in 6 rolled quads of 4 j: reload h once per quad (short
        // h2 liveness keeps registers bounded; 4x fewer h re-reads than R6)
        float o = sOb;
        for (int jq = 0; jq < 6; jq++) {
            ULL h2[24];
            #pragma unroll
            for (int m = 0; m < 12; m++) {
                ulonglong2 t = hsh[m * 96 + tid];
                h2[2 * m]     = t.x;
                h2[2 * m + 1] = t.y;
            }
            #pragma unroll
            for (int p = 0; p < 4; p++) {
                const int j = 4 * jq + p;
                const ulonglong2* dj = (const ulonglong2*)(sD + 80 * j);
                ULL acc = 0ULL;
                #pragma unroll
                for (int k = 0; k < 8; k++) {
                    ulonglong2 w = dj[k];
                    acc = fma2(x2[2 * k], w.x, acc);
                    acc = fma2(x2[2 * k + 1], w.y, acc);
                }
                #pragma unroll
                for (int m = 0; m < 12; m++) {
                    ulonglong2 w = dj[8 + m];
                    acc = fma2(h2[2 * m],     w.x, acc);
                    acc = fma2(h2[2 * m + 1], w.y, acc);
                }
                float hid = hsum2(acc) + sDb[j];
                hid = fmaxf(hid, 0.0f);
                o = fmaf(hid, sOw[j], o);
            }
        }
        out[b] = sigmoidf(o);

        // last-wins scatter of h_new
        if (b == winner) {
            float4* os = (float4*)(out_state + s * 48);
            #pragma unroll
            for (int m = 0; m < 12; m++) {
                ulonglong2 h = hsh[m * 96 + tid];
                float2 a = up2(h.x), c = up2(h.y);
                float4 v; v.x = a.x; v.y = a.y; v.z = c.x; v.w = c.y;
                os[m] = v;
            }
        }
    }
}

extern "C" void kernel_launch(void* const* d_in, const int* in_sizes, int n_in,
                              void* d_out, int out_size) {
    const float* inputs = (const float*)d_in[0];
    const int*   ids    = (const int*)d_in[1];
    const float* state  = (const float*)d_in[2];
    const float* Wk     = (const float*)d_in[3];
    const float* Urec   = (const float*)d_in[4];
    const float* gbias  = (const float*)d_in[5];
    const float* Dw     = (const float*)d_in[6];
    const float* Db     = (const float*)d_in[7];
    const float* Ow     = (const float*)d_in[8];
    const float* Ob     = (const float*)d_in[9];

    const int B = in_sizes[0] / 32;
    const int S = in_sizes[2] / 48;

    float* out       = (float*)d_out;
    float* out_state = out + B;

    setup_kernel<<<S + BIN_CTAS, 256>>>(state, Urec, out_state, ids, B);
    main_kernel<<<S * NCHUNK, 96>>>(inputs, state, Wk, gbias,
                                    Dw, Db, Ow, Ob, out, out_state);
}